// round 5
// baseline (speedup 1.0000x reference)
#include <cuda_runtime.h>

#define BS 8
#define NA 8400
#define NM 128
#define NC 80
#define TOPK 13
#define EPSF 1e-9f

#define G 8          // gts per k_topk block
#define MAXPOS 640   // per-gt positive-candidate buffer cap (8-sigma margin)

typedef unsigned long long ull;

// Scratch (no allocations allowed)
__device__ int   g_count[BS * NA];
__device__ int   g_am[BS * NA];
__device__ float g_cls[BS * NA];

// ---------------------------------------------------------------------------
// K1: warp-per-anchor class argmax (coalesced), + scratch init.
// ---------------------------------------------------------------------------
__global__ void k_argmax_init(const float* __restrict__ pd_scores) {
    int wid = threadIdx.x >> 5;
    int lane = threadIdx.x & 31;
    int anchor = blockIdx.x * 8 + wid;
    if (anchor >= BS * NA) return;
    const float* row = pd_scores + (size_t)anchor * NC;

    ull best = 0;
#pragma unroll
    for (int i = 0; i < 3; ++i) {
        int c = lane + i * 32;
        if (c < NC) {
            unsigned bits = __float_as_uint(row[c]);
            unsigned u = (bits & 0x80000000u) ? ~bits : (bits | 0x80000000u);
            ull key = ((ull)u << 32) | (unsigned)(~c);
            if (key > best) best = key;
        }
    }
#pragma unroll
    for (int off = 16; off > 0; off >>= 1) {
        ull o = __shfl_xor_sync(0xFFFFFFFFu, best, off);
        if (o > best) best = o;
    }
    if (lane == 0) g_cls[anchor] = (float)(~(unsigned)(best & 0xFFFFFFFFull));
    if (threadIdx.x < 8) {
        int a2 = blockIdx.x * 8 + threadIdx.x;
        if (a2 < BS * NA) { g_count[a2] = 0; g_am[a2] = 0x7FFFFFFF; }
    }
}

// ---------------------------------------------------------------------------
// K2: one block per (b, group of G gts). Phase 1 collects anchors with
// align > 0 into per-gt shared buffers. Phase 2: one warp per gt extracts
// top-13 (value desc, index asc) and updates count/am.
// ---------------------------------------------------------------------------
__global__ __launch_bounds__(512) void k_topk(const float* __restrict__ pd_boxes,
                                              const float* __restrict__ gt_boxes,
                                              const float* __restrict__ mask_gt) {
    __shared__ int  sn[G];
    __shared__ ull  keys[G][MAXPOS];
    __shared__ unsigned selbuf[G][TOPK];
    __shared__ float4 sg[G];
    __shared__ float  smk[G];

    int b = blockIdx.x / (NM / G);
    int mbase = (blockIdx.x % (NM / G)) * G;
    int tid = threadIdx.x;

    if (tid < G) {
        sn[tid] = 0;
        sg[tid] = ((const float4*)gt_boxes)[b * NM + mbase + tid];
        smk[tid] = mask_gt[b * NM + mbase + tid];
    }
    __syncthreads();

    float4 gr[G]; float ga[G]; bool act[G];
#pragma unroll
    for (int w = 0; w < G; ++w) {
        gr[w] = sg[w];
        ga[w] = (gr[w].z - gr[w].x) * (gr[w].w - gr[w].y);
        act[w] = (smk[w] != 0.0f);
    }

    const float4* pb = (const float4*)pd_boxes + (size_t)b * NA;
    const float*  cl = g_cls + (size_t)b * NA;

    for (int a = tid; a < NA; a += 512) {
        float4 p = __ldg(&pb[a]);
        float c = __ldg(&cl[a]);
        float area_p = (p.z - p.x) * (p.w - p.y);
        float cx = (p.x + p.z) * 0.5f, cy = (p.y + p.w) * 0.5f;
#pragma unroll
        for (int w = 0; w < G; ++w) {
            if (!act[w]) continue;
            float4 g = gr[w];
            float dmin = fminf(fminf(cx - g.x, cy - g.y), fminf(g.z - cx, g.w - cy));
            if (dmin > EPSF && c > 0.0f) {
                float lx = fmaxf(g.x, p.x), ly = fmaxf(g.y, p.y);
                float rx = fminf(g.z, p.z), ry = fminf(g.w, p.w);
                float iw = fmaxf(rx - lx, 0.0f), ih = fmaxf(ry - ly, 0.0f);
                float inter = iw * ih;
                float iou = inter / (ga[w] + area_p - inter + EPSF);
                float i2 = iou * iou;
                float al = c * ((i2 * i2) * i2);
                if (al > 0.0f) {
                    int pos = atomicAdd(&sn[w], 1);
                    if (pos < MAXPOS) {
                        keys[w][pos] = ((ull)__float_as_uint(al) << 32) |
                                       (unsigned)(~(unsigned)a);
                    }
                }
            }
        }
    }
    __syncthreads();

    int wid = tid >> 5, lane = tid & 31;
    if (wid < G) {
        int m = mbase + wid;
        if (!act[wid]) {
            if (lane < TOPK) {
                atomicAdd(&g_count[b * NA + lane], 1);
                atomicMin(&g_am[b * NA + lane], m);
            }
        } else {
            int n = min(sn[wid], MAXPOS);
            ull* K = keys[wid];
            int sel = min(n, TOPK);
            for (int r = 0; r < sel; ++r) {
                ull bk = 0; int bp = -1;
                for (int i = lane; i < n; i += 32) {
                    ull k = K[i];
                    if (k > bk) { bk = k; bp = i; }
                }
#pragma unroll
                for (int off = 16; off > 0; off >>= 1) {
                    ull ok = __shfl_xor_sync(0xFFFFFFFFu, bk, off);
                    int op = __shfl_xor_sync(0xFFFFFFFFu, bp, off);
                    if (ok > bk) { bk = ok; bp = op; }
                }
                if (lane == 0) {
                    unsigned aa = ~(unsigned)(bk & 0xFFFFFFFFull);
                    selbuf[wid][r] = aa;
                    atomicAdd(&g_count[b * NA + aa], 1);
                    atomicMin(&g_am[b * NA + aa], m);
                    K[bp] = 0;
                }
                __syncwarp();
            }
            __syncwarp();
            if (lane == 0 && n < TOPK) {
                int f = TOPK - n;
                for (int a = 0; f > 0; ++a) {
                    bool pos = false;
                    for (int i = 0; i < n; ++i)
                        if (selbuf[wid][i] == (unsigned)a) { pos = true; break; }
                    if (!pos) {
                        atomicAdd(&g_count[b * NA + a], 1);
                        atomicMin(&g_am[b * NA + a], m);
                        --f;
                    }
                }
            }
        }
    }
}

// ---------------------------------------------------------------------------
// K3: fused output kernel.
//  - count<=1 fast path per thread
//  - count>1: warp-cooperative 128-gt IoU argmax (exact first-m ties)
//  - one-hot ts written fully coalesced (float4) from shared labels
// ---------------------------------------------------------------------------
__global__ __launch_bounds__(256) void k_out(const float* __restrict__ pd_boxes,
                                             const int* __restrict__ gt_labels,
                                             const float* __restrict__ gt_boxes,
                                             float* __restrict__ out) {
    __shared__ int slabel[256];

    int base = blockIdx.x * 256;
    int idx = base + threadIdx.x;
    int lane = threadIdx.x & 31;
    bool valid = idx < BS * NA;

    int b = valid ? idx / NA : 0;
    int c = valid ? g_count[idx] : 0;
    int am = 0;
    float msk = 0.0f;
    if (c == 1) { am = g_am[idx]; msk = 1.0f; }

    // warp-cooperative resolution of multi-assigned anchors
    unsigned mm = __ballot_sync(0xFFFFFFFFu, c > 1);
    while (mm) {
        int src = __ffs(mm) - 1;
        mm &= mm - 1;
        int widx = __shfl_sync(0xFFFFFFFFu, idx, src);
        int wb = widx / NA;
        float4 p = ((const float4*)pd_boxes)[widx];
        float area_p = (p.z - p.x) * (p.w - p.y);
        const float4* gb = (const float4*)gt_boxes + (size_t)wb * NM;

        ull best = 0;
#pragma unroll
        for (int i = 0; i < NM / 32; ++i) {
            int m = lane + i * 32;
            float4 g = gb[m];
            float lx = fmaxf(g.x, p.x), ly = fmaxf(g.y, p.y);
            float rx = fminf(g.z, p.z), ry = fminf(g.w, p.w);
            float iw = fmaxf(rx - lx, 0.0f), ih = fmaxf(ry - ly, 0.0f);
            float inter = iw * ih;
            float area_g = (g.z - g.x) * (g.w - g.y);
            float iou = inter / (area_g + area_p - inter + EPSF);
            ull key = ((ull)__float_as_uint(iou) << 32) | (unsigned)(~(unsigned)m);
            if (key > best) best = key;
        }
#pragma unroll
        for (int off = 16; off > 0; off >>= 1) {
            ull o = __shfl_xor_sync(0xFFFFFFFFu, best, off);
            if (o > best) best = o;
        }
        int r_am = (int)(~(unsigned)(best & 0xFFFFFFFFull));
        if (lane == src) { am = r_am; msk = 1.0f; }
    }

    int lbl = NC;
    if (valid && msk > 0.0f) lbl = gt_labels[b * NM + am];
    slabel[threadIdx.x] = lbl;

    if (valid) {
        float* tl = out;
        float* tb = out + (size_t)BS * NA;
        float* mo = out + (size_t)BS * NA * 85;
        tl[idx] = (float)lbl;
        ((float4*)tb)[idx] = ((const float4*)gt_boxes)[b * NM + am];
        mo[idx] = msk;
    }
    __syncthreads();

    // coalesced one-hot write: 20 float4 quads per anchor
    int nloc = min(256, BS * NA - base);
    float4* tsp = (float4*)(out + (size_t)BS * NA * 5) + (size_t)base * (NC / 4);
    for (int i = threadIdx.x; i < nloc * (NC / 4); i += 256) {
        int al = i / (NC / 4);
        int q  = i - al * (NC / 4);
        int l2 = slabel[al];
        float4 v = make_float4(0.f, 0.f, 0.f, 0.f);
        if ((l2 >> 2) == q) ((float*)&v)[l2 & 3] = 1.0f;
        tsp[i] = v;
    }
}

// ---------------------------------------------------------------------------
extern "C" void kernel_launch(void* const* d_in, const int* in_sizes, int n_in,
                              void* d_out, int out_size) {
    const float* pd_scores = (const float*)d_in[0];
    const float* pd_boxes  = (const float*)d_in[1];
    const int*   gt_labels = (const int*)d_in[2];
    const float* gt_boxes  = (const float*)d_in[3];
    const float* mask_gt   = (const float*)d_in[4];
    float* out = (float*)d_out;

    int n = BS * NA;
    k_argmax_init<<<(n + 7) / 8, 256>>>(pd_scores);
    k_topk<<<BS * NM / G, 512>>>(pd_boxes, gt_boxes, mask_gt);
    k_out<<<(n + 255) / 256, 256>>>(pd_boxes, gt_labels, gt_boxes, out);
}

// round 6
// speedup vs baseline: 1.2838x; 1.2838x over previous
#include <cuda_runtime.h>

#define BS 8
#define NA 8400
#define NM 128
#define NC 80
#define TOPK 13
#define EPSF 1e-9f

#define G 8          // gts per k_topk block
#define MAXPOS 640   // per-gt positive-candidate buffer cap (8-sigma margin)
#define MAXMULTI 7168

#define NAB 8400                      // argmax blocks (8 anchors each)
#define NFILL4 (BS * NA * NC / 4)     // ts region in float4 units
#define FILLB ((NFILL4 + 511) / 512)  // fill blocks (512 float4 each)

typedef unsigned long long ull;

// Scratch (no allocations allowed)
__device__ int   g_count[BS * NA];
__device__ int   g_am[BS * NA];
__device__ float g_cls[BS * NA];
__device__ int   g_wcount;
__device__ int   g_wlist[MAXMULTI];

// ---------------------------------------------------------------------------
// K1: warp-per-anchor class argmax (lightweight fmax+imin reduction),
// scratch init, and fused coalesced zero-fill of the ts output region.
// ---------------------------------------------------------------------------
__global__ void k_argmax_init(const float* __restrict__ pd_scores,
                              float* __restrict__ out) {
    int bx = blockIdx.x;
    if (bx >= NAB) {
        // ts zero-fill region: 512 float4 per block, 2 per thread
        size_t i0 = (size_t)(bx - NAB) * 512 + threadIdx.x;
        float4* ts4 = (float4*)(out + (size_t)BS * NA * 5);
        float4 z = make_float4(0.f, 0.f, 0.f, 0.f);
        if (i0 < NFILL4) ts4[i0] = z;
        size_t i1 = i0 + 256;
        if (i1 < NFILL4) ts4[i1] = z;
        return;
    }

    if (bx == 0 && threadIdx.x == 0) g_wcount = 0;

    int wid = threadIdx.x >> 5;
    int lane = threadIdx.x & 31;
    int anchor = bx * 8 + wid;
    const float* row = pd_scores + (size_t)anchor * NC;

    // per-lane first-max over classes lane, lane+32, lane+64 (ascending)
    float bv = row[lane];
    int bi = lane;
    float v1 = row[lane + 32];
    if (v1 > bv) { bv = v1; bi = lane + 32; }
    if (lane < NC - 64) {
        float v2 = row[lane + 64];
        if (v2 > bv) { bv = v2; bi = lane + 64; }
    }

    // global max value
    float gm = bv;
#pragma unroll
    for (int off = 16; off > 0; off >>= 1)
        gm = fmaxf(gm, __shfl_xor_sync(0xFFFFFFFFu, gm, off));

    // smallest class index achieving the max
    int cand = (bv == gm) ? bi : 0x7FFFFFFF;
#pragma unroll
    for (int off = 16; off > 0; off >>= 1)
        cand = min(cand, __shfl_xor_sync(0xFFFFFFFFu, cand, off));

    if (lane == 0) g_cls[anchor] = (float)cand;
    if (threadIdx.x < 8) {
        int a2 = bx * 8 + threadIdx.x;
        g_count[a2] = 0;
        g_am[a2] = 0x7FFFFFFF;
    }
}

// ---------------------------------------------------------------------------
// K2: one block per (b, group of G gts). Phase 1 collects anchors with
// align > 0 into per-gt shared buffers. Phase 2: one warp per gt extracts
// top-13 (value desc, index asc) and updates count/am.
// ---------------------------------------------------------------------------
__global__ __launch_bounds__(512) void k_topk(const float* __restrict__ pd_boxes,
                                              const float* __restrict__ gt_boxes,
                                              const float* __restrict__ mask_gt) {
    __shared__ int  sn[G];
    __shared__ ull  keys[G][MAXPOS];
    __shared__ unsigned selbuf[G][TOPK];
    __shared__ float4 sg[G];
    __shared__ float  smk[G];

    int b = blockIdx.x / (NM / G);
    int mbase = (blockIdx.x % (NM / G)) * G;
    int tid = threadIdx.x;

    if (tid < G) {
        sn[tid] = 0;
        sg[tid] = ((const float4*)gt_boxes)[b * NM + mbase + tid];
        smk[tid] = mask_gt[b * NM + mbase + tid];
    }
    __syncthreads();

    float4 gr[G]; float ga[G]; bool act[G];
#pragma unroll
    for (int w = 0; w < G; ++w) {
        gr[w] = sg[w];
        ga[w] = (gr[w].z - gr[w].x) * (gr[w].w - gr[w].y);
        act[w] = (smk[w] != 0.0f);
    }

    const float4* pb = (const float4*)pd_boxes + (size_t)b * NA;
    const float*  cl = g_cls + (size_t)b * NA;

    for (int a = tid; a < NA; a += 512) {
        float4 p = __ldg(&pb[a]);
        float c = __ldg(&cl[a]);
        float area_p = (p.z - p.x) * (p.w - p.y);
        float cx = (p.x + p.z) * 0.5f, cy = (p.y + p.w) * 0.5f;
#pragma unroll
        for (int w = 0; w < G; ++w) {
            if (!act[w]) continue;
            float4 g = gr[w];
            float dmin = fminf(fminf(cx - g.x, cy - g.y), fminf(g.z - cx, g.w - cy));
            if (dmin > EPSF && c > 0.0f) {
                float lx = fmaxf(g.x, p.x), ly = fmaxf(g.y, p.y);
                float rx = fminf(g.z, p.z), ry = fminf(g.w, p.w);
                float iw = fmaxf(rx - lx, 0.0f), ih = fmaxf(ry - ly, 0.0f);
                float inter = iw * ih;
                float iou = inter / (ga[w] + area_p - inter + EPSF);
                float i2 = iou * iou;
                float al = c * ((i2 * i2) * i2);
                if (al > 0.0f) {
                    int pos = atomicAdd(&sn[w], 1);
                    if (pos < MAXPOS) {
                        keys[w][pos] = ((ull)__float_as_uint(al) << 32) |
                                       (unsigned)(~(unsigned)a);
                    }
                }
            }
        }
    }
    __syncthreads();

    int wid = tid >> 5, lane = tid & 31;
    if (wid < G) {
        int m = mbase + wid;
        if (!act[wid]) {
            if (lane < TOPK) {
                atomicAdd(&g_count[b * NA + lane], 1);
                atomicMin(&g_am[b * NA + lane], m);
            }
        } else {
            int n = min(sn[wid], MAXPOS);
            ull* K = keys[wid];
            int sel = min(n, TOPK);
            for (int r = 0; r < sel; ++r) {
                ull bk = 0; int bp = -1;
                for (int i = lane; i < n; i += 32) {
                    ull k = K[i];
                    if (k > bk) { bk = k; bp = i; }
                }
#pragma unroll
                for (int off = 16; off > 0; off >>= 1) {
                    ull ok = __shfl_xor_sync(0xFFFFFFFFu, bk, off);
                    int op = __shfl_xor_sync(0xFFFFFFFFu, bp, off);
                    if (ok > bk) { bk = ok; bp = op; }
                }
                if (lane == 0) {
                    unsigned aa = ~(unsigned)(bk & 0xFFFFFFFFull);
                    selbuf[wid][r] = aa;
                    atomicAdd(&g_count[b * NA + aa], 1);
                    atomicMin(&g_am[b * NA + aa], m);
                    K[bp] = 0;
                }
                __syncwarp();
            }
            __syncwarp();
            if (lane == 0 && n < TOPK) {
                int f = TOPK - n;
                for (int a = 0; f > 0; ++a) {
                    bool pos = false;
                    for (int i = 0; i < n; ++i)
                        if (selbuf[wid][i] == (unsigned)a) { pos = true; break; }
                    if (!pos) {
                        atomicAdd(&g_count[b * NA + a], 1);
                        atomicMin(&g_am[b * NA + a], m);
                        --f;
                    }
                }
            }
        }
    }
}

// ---------------------------------------------------------------------------
// K3: per-anchor fast path (count<=1) + multi-anchor worklist compression.
// ---------------------------------------------------------------------------
__global__ void k_out(const int* __restrict__ gt_labels,
                      const float* __restrict__ gt_boxes,
                      float* __restrict__ out) {
    int idx = blockIdx.x * blockDim.x + threadIdx.x;
    if (idx >= BS * NA) return;
    int b = idx / NA;

    int c = g_count[idx];
    if (c > 1) {
        int pos = atomicAdd(&g_wcount, 1);
        g_wlist[pos] = idx;
        return;   // outputs written by k_resolve
    }
    int am = 0;
    float msk = 0.0f;
    if (c == 1) { am = g_am[idx]; msk = 1.0f; }

    int lbl = (msk > 0.0f) ? gt_labels[b * NM + am] : NC;

    float* tl = out;
    float* tb = out + (size_t)BS * NA;
    float* ts = out + (size_t)BS * NA * 5;
    float* mo = out + (size_t)BS * NA * 85;

    tl[idx] = (float)lbl;
    ((float4*)tb)[idx] = ((const float4*)gt_boxes)[b * NM + am];
    if (lbl < NC) ts[(size_t)idx * NC + lbl] = 1.0f;
    mo[idx] = msk;
}

// ---------------------------------------------------------------------------
// K4: one warp per multi anchor. argmax_m IoU over ALL 128 gts
// (first m on ties) via packed-key shfl reduction; lane 0 emits outputs.
// ---------------------------------------------------------------------------
__global__ void k_resolve(const float* __restrict__ pd_boxes,
                          const int* __restrict__ gt_labels,
                          const float* __restrict__ gt_boxes,
                          float* __restrict__ out) {
    int lane = threadIdx.x & 31;
    int warp = (blockIdx.x * blockDim.x + threadIdx.x) >> 5;
    int nwarps = (gridDim.x * blockDim.x) >> 5;
    int wc = g_wcount;

    for (int e = warp; e < wc; e += nwarps) {
        int idx = g_wlist[e];
        int b = idx / NA;
        float4 p = ((const float4*)pd_boxes)[idx];
        float area_p = (p.z - p.x) * (p.w - p.y);
        const float4* gb = (const float4*)gt_boxes + (size_t)b * NM;

        ull best = 0;
#pragma unroll
        for (int i = 0; i < NM / 32; ++i) {
            int m = lane + i * 32;
            float4 g = gb[m];
            float lx = fmaxf(g.x, p.x), ly = fmaxf(g.y, p.y);
            float rx = fminf(g.z, p.z), ry = fminf(g.w, p.w);
            float iw = fmaxf(rx - lx, 0.0f), ih = fmaxf(ry - ly, 0.0f);
            float inter = iw * ih;
            float area_g = (g.z - g.x) * (g.w - g.y);
            float iou = inter / (area_g + area_p - inter + EPSF);
            ull key = ((ull)__float_as_uint(iou) << 32) | (unsigned)(~(unsigned)m);
            if (key > best) best = key;
        }
#pragma unroll
        for (int off = 16; off > 0; off >>= 1) {
            ull o = __shfl_xor_sync(0xFFFFFFFFu, best, off);
            if (o > best) best = o;
        }
        if (lane == 0) {
            int am = (int)(~(unsigned)(best & 0xFFFFFFFFull));
            int lbl = gt_labels[b * NM + am];
            float* tl = out;
            float* tb = out + (size_t)BS * NA;
            float* ts = out + (size_t)BS * NA * 5;
            float* mo = out + (size_t)BS * NA * 85;
            tl[idx] = (float)lbl;
            ((float4*)tb)[idx] = ((const float4*)gt_boxes)[b * NM + am];
            if (lbl < NC) ts[(size_t)idx * NC + lbl] = 1.0f;
            mo[idx] = 1.0f;
        }
    }
}

// ---------------------------------------------------------------------------
extern "C" void kernel_launch(void* const* d_in, const int* in_sizes, int n_in,
                              void* d_out, int out_size) {
    const float* pd_scores = (const float*)d_in[0];
    const float* pd_boxes  = (const float*)d_in[1];
    const int*   gt_labels = (const int*)d_in[2];
    const float* gt_boxes  = (const float*)d_in[3];
    const float* mask_gt   = (const float*)d_in[4];
    float* out = (float*)d_out;

    int n = BS * NA;
    k_argmax_init<<<NAB + FILLB, 256>>>(pd_scores, out);
    k_topk<<<BS * NM / G, 512>>>(pd_boxes, gt_boxes, mask_gt);
    k_out<<<(n + 255) / 256, 256>>>(gt_labels, gt_boxes, out);
    k_resolve<<<296, 256>>>(pd_boxes, gt_labels, gt_boxes, out);
}

// round 7
// speedup vs baseline: 1.2848x; 1.0007x over previous
#include <cuda_runtime.h>

#define BS 8
#define NA 8400
#define NM 128
#define NC 80
#define TOPK 13
#define EPSF 1e-9f

#define G 8          // gts per k_topk block
#define MAXPOS 640   // per-gt positive-candidate buffer cap (8-sigma margin)

#define NAB 8400                      // argmax blocks (8 anchors each)
#define NFILL4 (BS * NA * NC / 4)     // ts region in float4 units
#define FILLB ((NFILL4 + 511) / 512)  // fill blocks (512 float4 each)

typedef unsigned long long ull;

// Scratch (no allocations allowed)
__device__ int   g_count[BS * NA];
__device__ int   g_am[BS * NA];
__device__ float g_cls[BS * NA];

// ---------------------------------------------------------------------------
// K1: warp-per-anchor class argmax (lightweight fmax+imin reduction),
// scratch init, and fused coalesced zero-fill of the ts output region.
// ---------------------------------------------------------------------------
__global__ void k_argmax_init(const float* __restrict__ pd_scores,
                              float* __restrict__ out) {
    int bx = blockIdx.x;
    if (bx >= NAB) {
        // ts zero-fill region: 512 float4 per block, 2 per thread
        size_t i0 = (size_t)(bx - NAB) * 512 + threadIdx.x;
        float4* ts4 = (float4*)(out + (size_t)BS * NA * 5);
        float4 z = make_float4(0.f, 0.f, 0.f, 0.f);
        if (i0 < NFILL4) ts4[i0] = z;
        size_t i1 = i0 + 256;
        if (i1 < NFILL4) ts4[i1] = z;
        return;
    }

    int wid = threadIdx.x >> 5;
    int lane = threadIdx.x & 31;
    int anchor = bx * 8 + wid;
    const float* row = pd_scores + (size_t)anchor * NC;

    // per-lane first-max over classes lane, lane+32, lane+64 (ascending)
    float bv = row[lane];
    int bi = lane;
    float v1 = row[lane + 32];
    if (v1 > bv) { bv = v1; bi = lane + 32; }
    if (lane < NC - 64) {
        float v2 = row[lane + 64];
        if (v2 > bv) { bv = v2; bi = lane + 64; }
    }

    // global max value
    float gm = bv;
#pragma unroll
    for (int off = 16; off > 0; off >>= 1)
        gm = fmaxf(gm, __shfl_xor_sync(0xFFFFFFFFu, gm, off));

    // smallest class index achieving the max
    int cand = (bv == gm) ? bi : 0x7FFFFFFF;
#pragma unroll
    for (int off = 16; off > 0; off >>= 1)
        cand = min(cand, __shfl_xor_sync(0xFFFFFFFFu, cand, off));

    if (lane == 0) g_cls[anchor] = (float)cand;
    if (threadIdx.x < 8) {
        int a2 = bx * 8 + threadIdx.x;
        g_count[a2] = 0;
        g_am[a2] = 0x7FFFFFFF;
    }
}

// ---------------------------------------------------------------------------
// K2: one block per (b, group of G gts). Phase 1 collects anchors with
// align > 0 into per-gt shared buffers. Phase 2: one warp per gt extracts
// top-13 (value desc, index asc) and updates count/am.
// ---------------------------------------------------------------------------
__global__ __launch_bounds__(512) void k_topk(const float* __restrict__ pd_boxes,
                                              const float* __restrict__ gt_boxes,
                                              const float* __restrict__ mask_gt) {
    __shared__ int  sn[G];
    __shared__ ull  keys[G][MAXPOS];
    __shared__ unsigned selbuf[G][TOPK];
    __shared__ float4 sg[G];
    __shared__ float  smk[G];

    int b = blockIdx.x / (NM / G);
    int mbase = (blockIdx.x % (NM / G)) * G;
    int tid = threadIdx.x;

    if (tid < G) {
        sn[tid] = 0;
        sg[tid] = ((const float4*)gt_boxes)[b * NM + mbase + tid];
        smk[tid] = mask_gt[b * NM + mbase + tid];
    }
    __syncthreads();

    float4 gr[G]; float ga[G]; bool act[G];
#pragma unroll
    for (int w = 0; w < G; ++w) {
        gr[w] = sg[w];
        ga[w] = (gr[w].z - gr[w].x) * (gr[w].w - gr[w].y);
        act[w] = (smk[w] != 0.0f);
    }

    const float4* pb = (const float4*)pd_boxes + (size_t)b * NA;
    const float*  cl = g_cls + (size_t)b * NA;

    for (int a = tid; a < NA; a += 512) {
        float4 p = __ldg(&pb[a]);
        float c = __ldg(&cl[a]);
        float area_p = (p.z - p.x) * (p.w - p.y);
        float cx = (p.x + p.z) * 0.5f, cy = (p.y + p.w) * 0.5f;
#pragma unroll
        for (int w = 0; w < G; ++w) {
            if (!act[w]) continue;
            float4 g = gr[w];
            float dmin = fminf(fminf(cx - g.x, cy - g.y), fminf(g.z - cx, g.w - cy));
            if (dmin > EPSF && c > 0.0f) {
                float lx = fmaxf(g.x, p.x), ly = fmaxf(g.y, p.y);
                float rx = fminf(g.z, p.z), ry = fminf(g.w, p.w);
                float iw = fmaxf(rx - lx, 0.0f), ih = fmaxf(ry - ly, 0.0f);
                float inter = iw * ih;
                float iou = inter / (ga[w] + area_p - inter + EPSF);
                float i2 = iou * iou;
                float al = c * ((i2 * i2) * i2);
                if (al > 0.0f) {
                    int pos = atomicAdd(&sn[w], 1);
                    if (pos < MAXPOS) {
                        keys[w][pos] = ((ull)__float_as_uint(al) << 32) |
                                       (unsigned)(~(unsigned)a);
                    }
                }
            }
        }
    }
    __syncthreads();

    int wid = tid >> 5, lane = tid & 31;
    if (wid < G) {
        int m = mbase + wid;
        if (!act[wid]) {
            if (lane < TOPK) {
                atomicAdd(&g_count[b * NA + lane], 1);
                atomicMin(&g_am[b * NA + lane], m);
            }
        } else {
            int n = min(sn[wid], MAXPOS);
            ull* K = keys[wid];
            int sel = min(n, TOPK);
            for (int r = 0; r < sel; ++r) {
                ull bk = 0; int bp = -1;
                for (int i = lane; i < n; i += 32) {
                    ull k = K[i];
                    if (k > bk) { bk = k; bp = i; }
                }
#pragma unroll
                for (int off = 16; off > 0; off >>= 1) {
                    ull ok = __shfl_xor_sync(0xFFFFFFFFu, bk, off);
                    int op = __shfl_xor_sync(0xFFFFFFFFu, bp, off);
                    if (ok > bk) { bk = ok; bp = op; }
                }
                if (lane == 0) {
                    unsigned aa = ~(unsigned)(bk & 0xFFFFFFFFull);
                    selbuf[wid][r] = aa;
                    atomicAdd(&g_count[b * NA + aa], 1);
                    atomicMin(&g_am[b * NA + aa], m);
                    K[bp] = 0;
                }
                __syncwarp();
            }
            __syncwarp();
            if (lane == 0 && n < TOPK) {
                int f = TOPK - n;
                for (int a = 0; f > 0; ++a) {
                    bool pos = false;
                    for (int i = 0; i < n; ++i)
                        if (selbuf[wid][i] == (unsigned)a) { pos = true; break; }
                    if (!pos) {
                        atomicAdd(&g_count[b * NA + a], 1);
                        atomicMin(&g_am[b * NA + a], m);
                        --f;
                    }
                }
            }
        }
    }
}

// ---------------------------------------------------------------------------
// K3: per-anchor fast path (count<=1) + block-shared worklist for
// multi-assigned anchors, resolved warp-cooperatively after one barrier.
// ---------------------------------------------------------------------------
__global__ __launch_bounds__(256) void k_out(const float* __restrict__ pd_boxes,
                                             const int* __restrict__ gt_labels,
                                             const float* __restrict__ gt_boxes,
                                             float* __restrict__ out) {
    __shared__ int s_wn;
    __shared__ int s_wl[256];

    int base = blockIdx.x * 256;
    int tid = threadIdx.x;
    int idx = base + tid;
    bool valid = idx < BS * NA;
    if (tid == 0) s_wn = 0;
    __syncthreads();

    float* tl = out;
    float* tb = out + (size_t)BS * NA;
    float* ts = out + (size_t)BS * NA * 5;
    float* mo = out + (size_t)BS * NA * 85;

    if (valid) {
        int b = idx / NA;
        int c = g_count[idx];
        if (c > 1) {
            int pos = atomicAdd(&s_wn, 1);
            s_wl[pos] = tid;
        } else {
            int am = 0;
            float msk = 0.0f;
            if (c == 1) { am = g_am[idx]; msk = 1.0f; }
            int lbl = (msk > 0.0f) ? gt_labels[b * NM + am] : NC;
            tl[idx] = (float)lbl;
            ((float4*)tb)[idx] = ((const float4*)gt_boxes)[b * NM + am];
            if (lbl < NC) ts[(size_t)idx * NC + lbl] = 1.0f;
            mo[idx] = msk;
        }
    }
    __syncthreads();

    // warp-per-entry resolution of multi-assigned anchors
    int wid = tid >> 5, lane = tid & 31;
    int nw = s_wn;
    for (int e = wid; e < nw; e += 8) {
        int idx2 = base + s_wl[e];
        int b = idx2 / NA;
        float4 p = ((const float4*)pd_boxes)[idx2];
        float area_p = (p.z - p.x) * (p.w - p.y);
        const float4* gb = (const float4*)gt_boxes + (size_t)b * NM;

        ull best = 0;
#pragma unroll
        for (int i = 0; i < NM / 32; ++i) {
            int m = lane + i * 32;
            float4 g = gb[m];
            float lx = fmaxf(g.x, p.x), ly = fmaxf(g.y, p.y);
            float rx = fminf(g.z, p.z), ry = fminf(g.w, p.w);
            float iw = fmaxf(rx - lx, 0.0f), ih = fmaxf(ry - ly, 0.0f);
            float inter = iw * ih;
            float area_g = (g.z - g.x) * (g.w - g.y);
            float iou = inter / (area_g + area_p - inter + EPSF);
            ull key = ((ull)__float_as_uint(iou) << 32) | (unsigned)(~(unsigned)m);
            if (key > best) best = key;
        }
#pragma unroll
        for (int off = 16; off > 0; off >>= 1) {
            ull o = __shfl_xor_sync(0xFFFFFFFFu, best, off);
            if (o > best) best = o;
        }
        if (lane == 0) {
            int am = (int)(~(unsigned)(best & 0xFFFFFFFFull));
            int lbl = gt_labels[b * NM + am];
            tl[idx2] = (float)lbl;
            ((float4*)tb)[idx2] = ((const float4*)gt_boxes)[b * NM + am];
            if (lbl < NC) ts[(size_t)idx2 * NC + lbl] = 1.0f;
            mo[idx2] = 1.0f;
        }
    }
}

// ---------------------------------------------------------------------------
extern "C" void kernel_launch(void* const* d_in, const int* in_sizes, int n_in,
                              void* d_out, int out_size) {
    const float* pd_scores = (const float*)d_in[0];
    const float* pd_boxes  = (const float*)d_in[1];
    const int*   gt_labels = (const int*)d_in[2];
    const float* gt_boxes  = (const float*)d_in[3];
    const float* mask_gt   = (const float*)d_in[4];
    float* out = (float*)d_out;

    int n = BS * NA;
    k_argmax_init<<<NAB + FILLB, 256>>>(pd_scores, out);
    k_topk<<<BS * NM / G, 512>>>(pd_boxes, gt_boxes, mask_gt);
    k_out<<<(n + 255) / 256, 256>>>(pd_boxes, gt_labels, gt_boxes, out);
}

// round 10
// speedup vs baseline: 1.3489x; 1.0500x over previous
#include <cuda_runtime.h>

#define BS 8
#define NA 8400
#define NM 128
#define NC 80
#define TOPK 13
#define EPSF 1e-9f

#define G 8          // gts per topk block
#define MAXPOS 640   // per-gt positive-candidate buffer cap

typedef unsigned long long ull;

// Scratch (no allocations allowed)
__device__ int   g_count[BS * NA];
__device__ int   g_am[BS * NA];
__device__ float g_cls[BS * NA];

// ---------------------------------------------------------------------------
// K2: one block per (b, group of G gts). Phase 1 collects anchors with
// align > 0 into per-gt shared buffers. Phase 2: one warp per gt extracts
// top-13 (value desc, index asc) and updates count/am.
// ---------------------------------------------------------------------------
__global__ __launch_bounds__(512) void kern_topk(const float* __restrict__ pd_boxes,
                                                 const float* __restrict__ gt_boxes,
                                                 const float* __restrict__ mask_gt) {
    __shared__ int  sn[G];
    __shared__ ull  keys[G][MAXPOS];
    __shared__ unsigned selbuf[G][TOPK];
    __shared__ float4 sg[G];
    __shared__ float  smk[G];

    int b = blockIdx.x / (NM / G);
    int mbase = (blockIdx.x % (NM / G)) * G;
    int tid = threadIdx.x;

    if (tid < G) {
        sn[tid] = 0;
        sg[tid] = ((const float4*)gt_boxes)[b * NM + mbase + tid];
        smk[tid] = mask_gt[b * NM + mbase + tid];
    }
    __syncthreads();

    float4 gr[G]; float ga[G]; bool act[G];
#pragma unroll
    for (int w = 0; w < G; ++w) {
        gr[w] = sg[w];
        ga[w] = (gr[w].z - gr[w].x) * (gr[w].w - gr[w].y);
        act[w] = (smk[w] != 0.0f);
    }

    const float4* pb = (const float4*)pd_boxes + (size_t)b * NA;
    const float*  cl = g_cls + (size_t)b * NA;

    for (int a = tid; a < NA; a += 512) {
        float4 p = __ldg(&pb[a]);
        float c = __ldg(&cl[a]);
        float area_p = (p.z - p.x) * (p.w - p.y);
        float cx = (p.x + p.z) * 0.5f, cy = (p.y + p.w) * 0.5f;
#pragma unroll
        for (int w = 0; w < G; ++w) {
            if (!act[w]) continue;
            float4 g = gr[w];
            float dmin = fminf(fminf(cx - g.x, cy - g.y), fminf(g.z - cx, g.w - cy));
            if (dmin > EPSF && c > 0.0f) {
                float lx = fmaxf(g.x, p.x), ly = fmaxf(g.y, p.y);
                float rx = fminf(g.z, p.z), ry = fminf(g.w, p.w);
                float iw = fmaxf(rx - lx, 0.0f), ih = fmaxf(ry - ly, 0.0f);
                float inter = iw * ih;
                float iou = inter / (ga[w] + area_p - inter + EPSF);
                float i2 = iou * iou;
                float al = c * ((i2 * i2) * i2);
                if (al > 0.0f) {
                    int pos = atomicAdd(&sn[w], 1);
                    if (pos < MAXPOS) {
                        keys[w][pos] = ((ull)__float_as_uint(al) << 32) |
                                       (unsigned)(~(unsigned)a);
                    }
                }
            }
        }
    }
    __syncthreads();

    int wid = tid >> 5, lane = tid & 31;
    if (wid < G) {
        int m = mbase + wid;
        if (!act[wid]) {
            if (lane < TOPK) {
                atomicAdd(&g_count[b * NA + lane], 1);
                atomicMin(&g_am[b * NA + lane], m);
            }
        } else {
            int n = min(sn[wid], MAXPOS);
            ull* K = keys[wid];
            int sel = min(n, TOPK);
            for (int r = 0; r < sel; ++r) {
                ull bk = 0; int bp = -1;
                for (int i = lane; i < n; i += 32) {
                    ull k = K[i];
                    if (k > bk) { bk = k; bp = i; }
                }
#pragma unroll
                for (int off = 16; off > 0; off >>= 1) {
                    ull ok = __shfl_xor_sync(0xFFFFFFFFu, bk, off);
                    int op = __shfl_xor_sync(0xFFFFFFFFu, bp, off);
                    if (ok > bk) { bk = ok; bp = op; }
                }
                if (lane == 0) {
                    unsigned aa = ~(unsigned)(bk & 0xFFFFFFFFull);
                    selbuf[wid][r] = aa;
                    atomicAdd(&g_count[b * NA + aa], 1);
                    atomicMin(&g_am[b * NA + aa], m);
                    K[bp] = 0;
                }
                __syncwarp();
            }
            __syncwarp();
            if (lane == 0 && n < TOPK) {
                int f = TOPK - n;
                for (int a = 0; f > 0; ++a) {
                    bool pos = false;
                    for (int i = 0; i < n; ++i)
                        if (selbuf[wid][i] == (unsigned)a) { pos = true; break; }
                    if (!pos) {
                        atomicAdd(&g_count[b * NA + a], 1);
                        atomicMin(&g_am[b * NA + a], m);
                        --f;
                    }
                }
            }
        }
    }
}

// ---------------------------------------------------------------------------
// K1: pure class argmax, warp-per-anchor over 8 anchors/warp (64 per block),
// plus per-anchor scratch init. 1050 blocks of 256 threads.
// ---------------------------------------------------------------------------
__global__ __launch_bounds__(256) void kern_argmax(const float* __restrict__ pd_scores) {
    int abase = blockIdx.x * 64;
    if (threadIdx.x < 64) {
        g_count[abase + threadIdx.x] = 0;
        g_am[abase + threadIdx.x] = 0x7FFFFFFF;
    }

    int wid = threadIdx.x >> 5;
    int lane = threadIdx.x & 31;
    int a0 = abase + wid * 8;

    for (int it = 0; it < 8; ++it) {
        const float* row = pd_scores + (size_t)(a0 + it) * NC;

        float bv = row[lane];
        int bi = lane;
        float v1 = row[lane + 32];
        if (v1 > bv) { bv = v1; bi = lane + 32; }
        if (lane < 16) {
            float v2 = row[lane + 64];
            if (v2 > bv) { bv = v2; bi = lane + 64; }
        }

        float gm = bv;
        for (int off = 16; off > 0; off >>= 1)
            gm = fmaxf(gm, __shfl_xor_sync(0xFFFFFFFFu, gm, off));

        int cand = (bv == gm) ? bi : 0x7FFFFFFF;
        for (int off = 16; off > 0; off >>= 1)
            cand = min(cand, __shfl_xor_sync(0xFFFFFFFFu, cand, off));

        if (lane == 0) g_cls[a0 + it] = (float)cand;
    }
}

// ---------------------------------------------------------------------------
// K3: classify -> block-worklist multi resolution -> fully coalesced output
// emission, including the one-hot ts region (no separate zero-fill pass).
// s_res[t] = gt index in low 16 bits, bit 16 set => assigned (mask=1).
// ---------------------------------------------------------------------------
__global__ __launch_bounds__(256) void kern_out(const float* __restrict__ pd_boxes,
                                                const int* __restrict__ gt_labels,
                                                const float* __restrict__ gt_boxes,
                                                float* __restrict__ out) {
    __shared__ int s_wn;
    __shared__ int s_wl[256];
    __shared__ int s_res[256];
    __shared__ int s_lbl[256];

    int base = blockIdx.x * 256;
    int tid = threadIdx.x;
    int idx = base + tid;
    bool valid = idx < BS * NA;
    if (tid == 0) s_wn = 0;
    __syncthreads();

    // phase 1: classify
    int c = valid ? g_count[idx] : 0;
    int res = 0;                       // unassigned: am=0, mask=0
    if (c == 1) res = g_am[idx] | 0x10000;
    else if (c > 1) {
        int pos = atomicAdd(&s_wn, 1);
        s_wl[pos] = tid;
    }
    s_res[tid] = res;
    __syncthreads();

    // phase 2: warp-per-entry resolution of multi-assigned anchors
    int wid = tid >> 5, lane = tid & 31;
    int nw = s_wn;
    for (int e = wid; e < nw; e += 8) {
        int t2 = s_wl[e];
        int idx2 = base + t2;
        int b2 = idx2 / NA;
        float4 p = ((const float4*)pd_boxes)[idx2];
        float area_p = (p.z - p.x) * (p.w - p.y);
        const float4* gb = (const float4*)gt_boxes + (size_t)b2 * NM;

        ull best = 0;
        for (int i = 0; i < NM / 32; ++i) {
            int m = lane + i * 32;
            float4 g = gb[m];
            float lx = fmaxf(g.x, p.x), ly = fmaxf(g.y, p.y);
            float rx = fminf(g.z, p.z), ry = fminf(g.w, p.w);
            float iw = fmaxf(rx - lx, 0.0f), ih = fmaxf(ry - ly, 0.0f);
            float inter = iw * ih;
            float area_g = (g.z - g.x) * (g.w - g.y);
            float iou = inter / (area_g + area_p - inter + EPSF);
            ull key = ((ull)__float_as_uint(iou) << 32) | (unsigned)(~(unsigned)m);
            if (key > best) best = key;
        }
        for (int off = 16; off > 0; off >>= 1) {
            ull o = __shfl_xor_sync(0xFFFFFFFFu, best, off);
            if (o > best) best = o;
        }
        if (lane == 0)
            s_res[t2] = (int)(~(unsigned)(best & 0xFFFFFFFFull)) | 0x10000;
    }
    __syncthreads();

    // phase 3: per-thread scalar outputs
    float* tl = out;
    float* tb = out + (size_t)BS * NA;
    float* mo = out + (size_t)BS * NA * 85;

    int lbl = NC;
    if (valid) {
        int b = idx / NA;
        int r = s_res[tid];
        int am = r & 0xFFFF;
        float msk = (r & 0x10000) ? 1.0f : 0.0f;
        if (msk > 0.0f) lbl = gt_labels[b * NM + am];
        tl[idx] = (float)lbl;
        ((float4*)tb)[idx] = ((const float4*)gt_boxes)[b * NM + am];
        mo[idx] = msk;
    }
    s_lbl[tid] = lbl;
    __syncthreads();

    // phase 4: fully coalesced one-hot emission (20 float4 per anchor)
    int nloc = min(256, BS * NA - base);
    float4* tsp = (float4*)(out + (size_t)BS * NA * 5) + (size_t)base * (NC / 4);
    for (int i = tid; i < nloc * (NC / 4); i += 256) {
        int al = i / (NC / 4);
        int q  = i - al * (NC / 4);
        int l2 = s_lbl[al];
        float4 v = make_float4(0.f, 0.f, 0.f, 0.f);
        if ((l2 >> 2) == q) ((float*)&v)[l2 & 3] = 1.0f;
        tsp[i] = v;
    }
}

// ---------------------------------------------------------------------------
extern "C" void kernel_launch(void* const* d_in, const int* in_sizes, int n_in,
                              void* d_out, int out_size) {
    const float* pd_scores = (const float*)d_in[0];
    const float* pd_boxes  = (const float*)d_in[1];
    const int*   gt_labels = (const int*)d_in[2];
    const float* gt_boxes  = (const float*)d_in[3];
    const float* mask_gt   = (const float*)d_in[4];
    float* out = (float*)d_out;

    int n = BS * NA;
    kern_argmax<<<n / 64, 256>>>(pd_scores);
    kern_topk<<<BS * NM / G, 512>>>(pd_boxes, gt_boxes, mask_gt);
    kern_out<<<(n + 255) / 256, 256>>>(pd_boxes, gt_labels, gt_boxes, out);
}

// round 11
// speedup vs baseline: 1.4582x; 1.0810x over previous
#include <cuda_runtime.h>

#define BS 8
#define NA 8400
#define NM 128
#define NC 80
#define TOPK 13
#define EPSF 1e-9f

#define G 8          // gts per topk block
#define MAXPOS 640   // per-gt positive-candidate buffer cap

typedef unsigned long long ull;

// Scratch (no allocations allowed)
__device__ int   g_count[BS * NA];
__device__ int   g_am[BS * NA];
__device__ float g_cls[BS * NA];

// ---------------------------------------------------------------------------
// K2: one block per (b, group of G gts). Phase 1 collects anchors with
// align > 0 into per-gt shared buffers. Phase 2: one warp per gt extracts
// top-13 (value desc, index asc) and updates count/am.
// ---------------------------------------------------------------------------
__global__ __launch_bounds__(512) void kern_topk(const float* __restrict__ pd_boxes,
                                                 const float* __restrict__ gt_boxes,
                                                 const float* __restrict__ mask_gt) {
    __shared__ int  sn[G];
    __shared__ ull  keys[G][MAXPOS];
    __shared__ unsigned selbuf[G][TOPK];
    __shared__ float4 sg[G];
    __shared__ float  smk[G];

    int b = blockIdx.x / (NM / G);
    int mbase = (blockIdx.x % (NM / G)) * G;
    int tid = threadIdx.x;

    if (tid < G) {
        sn[tid] = 0;
        sg[tid] = ((const float4*)gt_boxes)[b * NM + mbase + tid];
        smk[tid] = mask_gt[b * NM + mbase + tid];
    }
    __syncthreads();

    float4 gr[G]; float ga[G]; bool act[G];
#pragma unroll
    for (int w = 0; w < G; ++w) {
        gr[w] = sg[w];
        ga[w] = (gr[w].z - gr[w].x) * (gr[w].w - gr[w].y);
        act[w] = (smk[w] != 0.0f);
    }

    const float4* pb = (const float4*)pd_boxes + (size_t)b * NA;
    const float*  cl = g_cls + (size_t)b * NA;

    for (int a = tid; a < NA; a += 512) {
        float4 p = __ldg(&pb[a]);
        float c = __ldg(&cl[a]);
        float area_p = (p.z - p.x) * (p.w - p.y);
        float cx = (p.x + p.z) * 0.5f, cy = (p.y + p.w) * 0.5f;
#pragma unroll
        for (int w = 0; w < G; ++w) {
            if (!act[w]) continue;
            float4 g = gr[w];
            float dmin = fminf(fminf(cx - g.x, cy - g.y), fminf(g.z - cx, g.w - cy));
            if (dmin > EPSF && c > 0.0f) {
                float lx = fmaxf(g.x, p.x), ly = fmaxf(g.y, p.y);
                float rx = fminf(g.z, p.z), ry = fminf(g.w, p.w);
                float iw = fmaxf(rx - lx, 0.0f), ih = fmaxf(ry - ly, 0.0f);
                float inter = iw * ih;
                float iou = inter / (ga[w] + area_p - inter + EPSF);
                float i2 = iou * iou;
                float al = c * ((i2 * i2) * i2);
                if (al > 0.0f) {
                    int pos = atomicAdd(&sn[w], 1);
                    if (pos < MAXPOS) {
                        keys[w][pos] = ((ull)__float_as_uint(al) << 32) |
                                       (unsigned)(~(unsigned)a);
                    }
                }
            }
        }
    }
    __syncthreads();

    int wid = tid >> 5, lane = tid & 31;
    if (wid < G) {
        int m = mbase + wid;
        if (!act[wid]) {
            if (lane < TOPK) {
                atomicAdd(&g_count[b * NA + lane], 1);
                atomicMin(&g_am[b * NA + lane], m);
            }
        } else {
            int n = min(sn[wid], MAXPOS);
            ull* K = keys[wid];
            int sel = min(n, TOPK);
            for (int r = 0; r < sel; ++r) {
                ull bk = 0; int bp = -1;
                for (int i = lane; i < n; i += 32) {
                    ull k = K[i];
                    if (k > bk) { bk = k; bp = i; }
                }
#pragma unroll
                for (int off = 16; off > 0; off >>= 1) {
                    ull ok = __shfl_xor_sync(0xFFFFFFFFu, bk, off);
                    int op = __shfl_xor_sync(0xFFFFFFFFu, bp, off);
                    if (ok > bk) { bk = ok; bp = op; }
                }
                if (lane == 0) {
                    unsigned aa = ~(unsigned)(bk & 0xFFFFFFFFull);
                    selbuf[wid][r] = aa;
                    atomicAdd(&g_count[b * NA + aa], 1);
                    atomicMin(&g_am[b * NA + aa], m);
                    K[bp] = 0;
                }
                __syncwarp();
            }
            __syncwarp();
            if (lane == 0 && n < TOPK) {
                int f = TOPK - n;
                for (int a = 0; f > 0; ++a) {
                    bool pos = false;
                    for (int i = 0; i < n; ++i)
                        if (selbuf[wid][i] == (unsigned)a) { pos = true; break; }
                    if (!pos) {
                        atomicAdd(&g_count[b * NA + a], 1);
                        atomicMin(&g_am[b * NA + a], m);
                        --f;
                    }
                }
            }
        }
    }
}

// ---------------------------------------------------------------------------
// K1: class argmax with 4 lanes per anchor, float4 loads (5 per lane, MLP=5),
// and only 4 shuffle rounds per anchor. 64 anchors/block, 1050 blocks.
// First-max semantics: per-lane strict-> scan in ascending class order, then
// group-max + min-index-among-equal reduction.
// ---------------------------------------------------------------------------
__global__ __launch_bounds__(256) void kern_argmax(const float* __restrict__ pd_scores) {
    int abase = blockIdx.x * 64;
    if (threadIdx.x < 64) {
        g_count[abase + threadIdx.x] = 0;
        g_am[abase + threadIdx.x] = 0x7FFFFFFF;
    }

    int wid = threadIdx.x >> 5;
    int lane = threadIdx.x & 31;
    int grp = lane >> 2;      // anchor group within warp (0..7)
    int j = lane & 3;         // lane within group
    int anchor = abase + wid * 8 + grp;

    const float4* r4 = (const float4*)(pd_scores + (size_t)anchor * NC);

    // load 5 float4s: classes 16k + 4j + {0..3}, k ascending => ascending order
    float4 v[5];
#pragma unroll
    for (int k = 0; k < 5; ++k) v[k] = __ldg(&r4[j + 4 * k]);

    float bv = v[0].x;
    int bi = 4 * j;
#pragma unroll
    for (int k = 0; k < 5; ++k) {
        int cbase = 16 * k + 4 * j;
        float a0 = v[k].x, a1 = v[k].y, a2 = v[k].z, a3 = v[k].w;
        if (a0 > bv) { bv = a0; bi = cbase + 0; }
        if (a1 > bv) { bv = a1; bi = cbase + 1; }
        if (a2 > bv) { bv = a2; bi = cbase + 2; }
        if (a3 > bv) { bv = a3; bi = cbase + 3; }
    }

    // group max over 4 lanes
    float gm = bv;
    gm = fmaxf(gm, __shfl_xor_sync(0xFFFFFFFFu, gm, 1));
    gm = fmaxf(gm, __shfl_xor_sync(0xFFFFFFFFu, gm, 2));

    // smallest class index achieving the max
    int cand = (bv == gm) ? bi : 0x7FFFFFFF;
    cand = min(cand, __shfl_xor_sync(0xFFFFFFFFu, cand, 1));
    cand = min(cand, __shfl_xor_sync(0xFFFFFFFFu, cand, 2));

    if (j == 0) g_cls[anchor] = (float)cand;
}

// ---------------------------------------------------------------------------
// K3: classify -> block-worklist multi resolution -> fully coalesced output
// emission, including the one-hot ts region (no separate zero-fill pass).
// s_res[t] = gt index in low 16 bits, bit 16 set => assigned (mask=1).
// ---------------------------------------------------------------------------
__global__ __launch_bounds__(256) void kern_out(const float* __restrict__ pd_boxes,
                                                const int* __restrict__ gt_labels,
                                                const float* __restrict__ gt_boxes,
                                                float* __restrict__ out) {
    __shared__ int s_wn;
    __shared__ int s_wl[256];
    __shared__ int s_res[256];
    __shared__ int s_lbl[256];

    int base = blockIdx.x * 256;
    int tid = threadIdx.x;
    int idx = base + tid;
    bool valid = idx < BS * NA;
    if (tid == 0) s_wn = 0;
    __syncthreads();

    // phase 1: classify
    int c = valid ? g_count[idx] : 0;
    int res = 0;                       // unassigned: am=0, mask=0
    if (c == 1) res = g_am[idx] | 0x10000;
    else if (c > 1) {
        int pos = atomicAdd(&s_wn, 1);
        s_wl[pos] = tid;
    }
    s_res[tid] = res;
    __syncthreads();

    // phase 2: warp-per-entry resolution of multi-assigned anchors
    int wid = tid >> 5, lane = tid & 31;
    int nw = s_wn;
    for (int e = wid; e < nw; e += 8) {
        int t2 = s_wl[e];
        int idx2 = base + t2;
        int b2 = idx2 / NA;
        float4 p = ((const float4*)pd_boxes)[idx2];
        float area_p = (p.z - p.x) * (p.w - p.y);
        const float4* gb = (const float4*)gt_boxes + (size_t)b2 * NM;

        ull best = 0;
        for (int i = 0; i < NM / 32; ++i) {
            int m = lane + i * 32;
            float4 g = gb[m];
            float lx = fmaxf(g.x, p.x), ly = fmaxf(g.y, p.y);
            float rx = fminf(g.z, p.z), ry = fminf(g.w, p.w);
            float iw = fmaxf(rx - lx, 0.0f), ih = fmaxf(ry - ly, 0.0f);
            float inter = iw * ih;
            float area_g = (g.z - g.x) * (g.w - g.y);
            float iou = inter / (area_g + area_p - inter + EPSF);
            ull key = ((ull)__float_as_uint(iou) << 32) | (unsigned)(~(unsigned)m);
            if (key > best) best = key;
        }
        for (int off = 16; off > 0; off >>= 1) {
            ull o = __shfl_xor_sync(0xFFFFFFFFu, best, off);
            if (o > best) best = o;
        }
        if (lane == 0)
            s_res[t2] = (int)(~(unsigned)(best & 0xFFFFFFFFull)) | 0x10000;
    }
    __syncthreads();

    // phase 3: per-thread scalar outputs
    float* tl = out;
    float* tb = out + (size_t)BS * NA;
    float* mo = out + (size_t)BS * NA * 85;

    int lbl = NC;
    if (valid) {
        int b = idx / NA;
        int r = s_res[tid];
        int am = r & 0xFFFF;
        float msk = (r & 0x10000) ? 1.0f : 0.0f;
        if (msk > 0.0f) lbl = gt_labels[b * NM + am];
        tl[idx] = (float)lbl;
        ((float4*)tb)[idx] = ((const float4*)gt_boxes)[b * NM + am];
        mo[idx] = msk;
    }
    s_lbl[tid] = lbl;
    __syncthreads();

    // phase 4: fully coalesced one-hot emission (20 float4 per anchor)
    int nloc = min(256, BS * NA - base);
    float4* tsp = (float4*)(out + (size_t)BS * NA * 5) + (size_t)base * (NC / 4);
    for (int i = tid; i < nloc * (NC / 4); i += 256) {
        int al = i / (NC / 4);
        int q  = i - al * (NC / 4);
        int l2 = s_lbl[al];
        float4 v = make_float4(0.f, 0.f, 0.f, 0.f);
        if ((l2 >> 2) == q) ((float*)&v)[l2 & 3] = 1.0f;
        tsp[i] = v;
    }
}

// ---------------------------------------------------------------------------
extern "C" void kernel_launch(void* const* d_in, const int* in_sizes, int n_in,
                              void* d_out, int out_size) {
    const float* pd_scores = (const float*)d_in[0];
    const float* pd_boxes  = (const float*)d_in[1];
    const int*   gt_labels = (const int*)d_in[2];
    const float* gt_boxes  = (const float*)d_in[3];
    const float* mask_gt   = (const float*)d_in[4];
    float* out = (float*)d_out;

    int n = BS * NA;
    kern_argmax<<<n / 64, 256>>>(pd_scores);
    kern_topk<<<BS * NM / G, 512>>>(pd_boxes, gt_boxes, mask_gt);
    kern_out<<<(n + 255) / 256, 256>>>(pd_boxes, gt_labels, gt_boxes, out);
}

// round 12
// speedup vs baseline: 1.6809x; 1.1527x over previous
#include <cuda_runtime.h>

#define BS 8
#define NA 8400
#define NM 128
#define NC 80
#define TOPK 13
#define EPSF 1e-9f

#define G 8          // gts per topk block
#define MAXPOS 640   // per-gt positive-candidate buffer cap
#define TKT 1024     // topk threads per block

typedef unsigned long long ull;

// Scratch (no allocations allowed)
__device__ int   g_count[BS * NA];
__device__ int   g_am[BS * NA];
__device__ float g_cls[BS * NA];

// ---------------------------------------------------------------------------
// K2: one block per (b, group of G gts), 1024 threads. Phase 1 collects
// anchors with align > 0 into per-gt shared buffers. Phase 2: one warp per gt
// extracts top-13 (value desc, index asc) and updates count/am.
// ---------------------------------------------------------------------------
__global__ __launch_bounds__(TKT) void kern_topk(const float* __restrict__ pd_boxes,
                                                 const float* __restrict__ gt_boxes,
                                                 const float* __restrict__ mask_gt) {
    __shared__ int  sn[G];
    __shared__ ull  keys[G][MAXPOS];
    __shared__ unsigned selbuf[G][TOPK];
    __shared__ float4 sg[G];
    __shared__ float  smk[G];

    int b = blockIdx.x / (NM / G);
    int mbase = (blockIdx.x % (NM / G)) * G;
    int tid = threadIdx.x;

    if (tid < G) {
        sn[tid] = 0;
        sg[tid] = ((const float4*)gt_boxes)[b * NM + mbase + tid];
        smk[tid] = mask_gt[b * NM + mbase + tid];
    }
    __syncthreads();

    float4 gr[G]; float ga[G]; bool act[G];
#pragma unroll
    for (int w = 0; w < G; ++w) {
        gr[w] = sg[w];
        ga[w] = (gr[w].z - gr[w].x) * (gr[w].w - gr[w].y);
        act[w] = (smk[w] != 0.0f);
    }

    const float4* pb = (const float4*)pd_boxes + (size_t)b * NA;
    const float*  cl = g_cls + (size_t)b * NA;

    for (int a = tid; a < NA; a += TKT) {
        float4 p = __ldg(&pb[a]);
        float c = __ldg(&cl[a]);
        float area_p = (p.z - p.x) * (p.w - p.y);
        float cx = (p.x + p.z) * 0.5f, cy = (p.y + p.w) * 0.5f;
#pragma unroll
        for (int w = 0; w < G; ++w) {
            if (!act[w]) continue;
            float4 g = gr[w];
            float dmin = fminf(fminf(cx - g.x, cy - g.y), fminf(g.z - cx, g.w - cy));
            if (dmin > EPSF && c > 0.0f) {
                float lx = fmaxf(g.x, p.x), ly = fmaxf(g.y, p.y);
                float rx = fminf(g.z, p.z), ry = fminf(g.w, p.w);
                float iw = fmaxf(rx - lx, 0.0f), ih = fmaxf(ry - ly, 0.0f);
                float inter = iw * ih;
                float iou = inter / (ga[w] + area_p - inter + EPSF);
                float i2 = iou * iou;
                float al = c * ((i2 * i2) * i2);
                if (al > 0.0f) {
                    int pos = atomicAdd(&sn[w], 1);
                    if (pos < MAXPOS) {
                        keys[w][pos] = ((ull)__float_as_uint(al) << 32) |
                                       (unsigned)(~(unsigned)a);
                    }
                }
            }
        }
    }
    __syncthreads();

    int wid = tid >> 5, lane = tid & 31;
    if (wid < G) {
        int m = mbase + wid;
        if (!act[wid]) {
            if (lane < TOPK) {
                atomicAdd(&g_count[b * NA + lane], 1);
                atomicMin(&g_am[b * NA + lane], m);
            }
        } else {
            int n = min(sn[wid], MAXPOS);
            ull* K = keys[wid];
            int sel = min(n, TOPK);
            for (int r = 0; r < sel; ++r) {
                ull bk = 0; int bp = -1;
                for (int i = lane; i < n; i += 32) {
                    ull k = K[i];
                    if (k > bk) { bk = k; bp = i; }
                }
#pragma unroll
                for (int off = 16; off > 0; off >>= 1) {
                    ull ok = __shfl_xor_sync(0xFFFFFFFFu, bk, off);
                    int op = __shfl_xor_sync(0xFFFFFFFFu, bp, off);
                    if (ok > bk) { bk = ok; bp = op; }
                }
                if (lane == 0) {
                    unsigned aa = ~(unsigned)(bk & 0xFFFFFFFFull);
                    selbuf[wid][r] = aa;
                    atomicAdd(&g_count[b * NA + aa], 1);
                    atomicMin(&g_am[b * NA + aa], m);
                    K[bp] = 0;
                }
                __syncwarp();
            }
            __syncwarp();
            if (lane == 0 && n < TOPK) {
                int f = TOPK - n;
                for (int a = 0; f > 0; ++a) {
                    bool pos = false;
                    for (int i = 0; i < n; ++i)
                        if (selbuf[wid][i] == (unsigned)a) { pos = true; break; }
                    if (!pos) {
                        atomicAdd(&g_count[b * NA + a], 1);
                        atomicMin(&g_am[b * NA + a], m);
                        --f;
                    }
                }
            }
        }
    }
}

// ---------------------------------------------------------------------------
// K1: class argmax with 4 lanes per anchor, 2 anchors per lane group.
// 10 independent float4 loads per lane (MLP=10), 4 shuffle rounds per anchor.
// 128 anchors/block, 525 blocks.
// ---------------------------------------------------------------------------
__global__ __launch_bounds__(256) void kern_argmax(const float* __restrict__ pd_scores) {
    int abase = blockIdx.x * 128;
    if (threadIdx.x < 128) {
        g_count[abase + threadIdx.x] = 0;
        g_am[abase + threadIdx.x] = 0x7FFFFFFF;
    }

    int wid = threadIdx.x >> 5;
    int lane = threadIdx.x & 31;
    int grp = lane >> 2;      // group within warp (0..7)
    int j = lane & 3;         // lane within group
    int a0 = abase + wid * 16 + grp * 2;

    const float4* r40 = (const float4*)(pd_scores + (size_t)a0 * NC);
    const float4* r41 = (const float4*)(pd_scores + (size_t)(a0 + 1) * NC);

    // issue all 10 loads up front (classes 16k + 4j + {0..3}, k ascending)
    float4 v0[5], v1[5];
#pragma unroll
    for (int k = 0; k < 5; ++k) v0[k] = __ldg(&r40[j + 4 * k]);
#pragma unroll
    for (int k = 0; k < 5; ++k) v1[k] = __ldg(&r41[j + 4 * k]);

#pragma unroll
    for (int t = 0; t < 2; ++t) {
        float4* v = t ? v1 : v0;
        float bv = v[0].x;
        int bi = 4 * j;
#pragma unroll
        for (int k = 0; k < 5; ++k) {
            int cbase = 16 * k + 4 * j;
            if (v[k].x > bv) { bv = v[k].x; bi = cbase + 0; }
            if (v[k].y > bv) { bv = v[k].y; bi = cbase + 1; }
            if (v[k].z > bv) { bv = v[k].z; bi = cbase + 2; }
            if (v[k].w > bv) { bv = v[k].w; bi = cbase + 3; }
        }

        float gm = bv;
        gm = fmaxf(gm, __shfl_xor_sync(0xFFFFFFFFu, gm, 1));
        gm = fmaxf(gm, __shfl_xor_sync(0xFFFFFFFFu, gm, 2));

        int cand = (bv == gm) ? bi : 0x7FFFFFFF;
        cand = min(cand, __shfl_xor_sync(0xFFFFFFFFu, cand, 1));
        cand = min(cand, __shfl_xor_sync(0xFFFFFFFFu, cand, 2));

        if (j == 0) g_cls[a0 + t] = (float)cand;
    }
}

// ---------------------------------------------------------------------------
// K3: classify -> block-worklist multi resolution -> fully coalesced output
// emission, including the one-hot ts region.
// s_res[t] = gt index in low 16 bits, bit 16 set => assigned (mask=1).
// ---------------------------------------------------------------------------
__global__ __launch_bounds__(256) void kern_out(const float* __restrict__ pd_boxes,
                                                const int* __restrict__ gt_labels,
                                                const float* __restrict__ gt_boxes,
                                                float* __restrict__ out) {
    __shared__ int s_wn;
    __shared__ int s_wl[256];
    __shared__ int s_res[256];
    __shared__ int s_lbl[256];

    int base = blockIdx.x * 256;
    int tid = threadIdx.x;
    int idx = base + tid;
    bool valid = idx < BS * NA;
    if (tid == 0) s_wn = 0;
    __syncthreads();

    // phase 1: classify
    int c = valid ? g_count[idx] : 0;
    int res = 0;                       // unassigned: am=0, mask=0
    if (c == 1) res = g_am[idx] | 0x10000;
    else if (c > 1) {
        int pos = atomicAdd(&s_wn, 1);
        s_wl[pos] = tid;
    }
    s_res[tid] = res;
    __syncthreads();

    // phase 2: warp-per-entry resolution of multi-assigned anchors
    int wid = tid >> 5, lane = tid & 31;
    int nw = s_wn;
    for (int e = wid; e < nw; e += 8) {
        int t2 = s_wl[e];
        int idx2 = base + t2;
        int b2 = idx2 / NA;
        float4 p = ((const float4*)pd_boxes)[idx2];
        float area_p = (p.z - p.x) * (p.w - p.y);
        const float4* gb = (const float4*)gt_boxes + (size_t)b2 * NM;

        ull best = 0;
        for (int i = 0; i < NM / 32; ++i) {
            int m = lane + i * 32;
            float4 g = gb[m];
            float lx = fmaxf(g.x, p.x), ly = fmaxf(g.y, p.y);
            float rx = fminf(g.z, p.z), ry = fminf(g.w, p.w);
            float iw = fmaxf(rx - lx, 0.0f), ih = fmaxf(ry - ly, 0.0f);
            float inter = iw * ih;
            float area_g = (g.z - g.x) * (g.w - g.y);
            float iou = inter / (area_g + area_p - inter + EPSF);
            ull key = ((ull)__float_as_uint(iou) << 32) | (unsigned)(~(unsigned)m);
            if (key > best) best = key;
        }
        for (int off = 16; off > 0; off >>= 1) {
            ull o = __shfl_xor_sync(0xFFFFFFFFu, best, off);
            if (o > best) best = o;
        }
        if (lane == 0)
            s_res[t2] = (int)(~(unsigned)(best & 0xFFFFFFFFull)) | 0x10000;
    }
    __syncthreads();

    // phase 3: per-thread scalar outputs
    float* tl = out;
    float* tb = out + (size_t)BS * NA;
    float* mo = out + (size_t)BS * NA * 85;

    int lbl = NC;
    if (valid) {
        int b = idx / NA;
        int r = s_res[tid];
        int am = r & 0xFFFF;
        float msk = (r & 0x10000) ? 1.0f : 0.0f;
        if (msk > 0.0f) lbl = gt_labels[b * NM + am];
        tl[idx] = (float)lbl;
        ((float4*)tb)[idx] = ((const float4*)gt_boxes)[b * NM + am];
        mo[idx] = msk;
    }
    s_lbl[tid] = lbl;
    __syncthreads();

    // phase 4: fully coalesced one-hot emission (20 float4 per anchor)
    int nloc = min(256, BS * NA - base);
    float4* tsp = (float4*)(out + (size_t)BS * NA * 5) + (size_t)base * (NC / 4);
    for (int i = tid; i < nloc * (NC / 4); i += 256) {
        int al = i / (NC / 4);
        int q  = i - al * (NC / 4);
        int l2 = s_lbl[al];
        float4 v = make_float4(0.f, 0.f, 0.f, 0.f);
        if ((l2 >> 2) == q) ((float*)&v)[l2 & 3] = 1.0f;
        tsp[i] = v;
    }
}

// ---------------------------------------------------------------------------
extern "C" void kernel_launch(void* const* d_in, const int* in_sizes, int n_in,
                              void* d_out, int out_size) {
    const float* pd_scores = (const float*)d_in[0];
    const float* pd_boxes  = (const float*)d_in[1];
    const int*   gt_labels = (const int*)d_in[2];
    const float* gt_boxes  = (const float*)d_in[3];
    const float* mask_gt   = (const float*)d_in[4];
    float* out = (float*)d_out;

    int n = BS * NA;
    kern_argmax<<<n / 128, 256>>>(pd_scores);
    kern_topk<<<BS * NM / G, TKT>>>(pd_boxes, gt_boxes, mask_gt);
    kern_out<<<(n + 255) / 256, 256>>>(pd_boxes, gt_labels, gt_boxes, out);
}